// round 16
// baseline (speedup 1.0000x reference)
#include <cuda_runtime.h>
#include <cstdint>

#define BATCH 128
#define NAG   64
#define NEDGE 4032
#define DN    16
#define HDIM  64
#define DOUT  16

// ---------------- scratch (no cudaMalloc) ----------------
__device__ float g_A0[BATCH * NAG * HDIM];
__device__ float g_C0[BATCH * NAG * HDIM];
__device__ float g_A1[BATCH * NAG * HDIM];
__device__ float g_C1[BATCH * NAG * HDIM];
__device__ float g_msgT[2 * BATCH * NAG * HDIM];
// W2 A-operand fragments: [t][jt(4)][kt(4)][hl(2)][lane(32)][4] u32 (bf16x2)
__device__ uint32_t g_Wf[2 * 4 * 4 * 2 * 32 * 4];

// ---------------- helpers ----------------
__device__ __forceinline__ uint32_t pkbf(float lok, float hik) {
    uint32_t d;
    asm("cvt.rn.bf16x2.f32 %0, %1, %2;" : "=r"(d) : "f"(hik), "f"(lok));
    return d;
}
__device__ __forceinline__ float bf_lo(uint32_t u) { return __uint_as_float(u << 16); }
__device__ __forceinline__ float bf_hi(uint32_t u) { return __uint_as_float(u & 0xffff0000u); }

__device__ __forceinline__ void mma_bf16(float c[4], uint4 a, uint2 b) {
    asm volatile(
        "mma.sync.aligned.m16n8k16.row.col.f32.bf16.bf16.f32 "
        "{%0,%1,%2,%3}, {%4,%5,%6,%7}, {%8,%9}, {%0,%1,%2,%3};"
        : "+f"(c[0]), "+f"(c[1]), "+f"(c[2]), "+f"(c[3])
        : "r"(a.x), "r"(a.y), "r"(a.z), "r"(a.w), "r"(b.x), "r"(b.y));
}

// Hw layout (R14, proven conflict-free): plane(recv,hl) stride PL; kt tiles at
// KTS(kt) = kt*576 + {0,2,16,18} bank perm; st rows stride 68.
#define STR  68
#define KTS(kt) ((kt) * 576 + (((kt) & 1) * 2) + (((kt) >> 1) * 16))
#define PL   2304

// ---------------- K0: W2 -> bf16 hi/lo A-operand fragments ----------------
__global__ __launch_bounds__(64) void k0_wfrag(
    const float* __restrict__ e0w2, const float* __restrict__ e1w2)
{
    int blk = blockIdx.x;              // 0..31 : t*16 + jt*4 + kt
    int t  = blk >> 4;
    int jt = (blk >> 2) & 3;
    int kt = blk & 3;
    int tid = threadIdx.x;
    int hl  = tid >> 5;
    int lane = tid & 31;
    int g4 = lane >> 2, t4 = lane & 3;

    const float* w2t = t ? e1w2 : e0w2;
    int K0 = kt * 16 + 2 * t4;
    int J  = jt * 16 + g4;

    float w00 = w2t[K0 * HDIM + J],       w01 = w2t[(K0 + 1) * HDIM + J];
    float w10 = w2t[K0 * HDIM + J + 8],   w11 = w2t[(K0 + 1) * HDIM + J + 8];
    float w20 = w2t[(K0 + 8) * HDIM + J], w21 = w2t[(K0 + 9) * HDIM + J];
    float w30 = w2t[(K0 + 8) * HDIM + J + 8], w31 = w2t[(K0 + 9) * HDIM + J + 8];

    uint4 H;
    H.x = pkbf(w00, w01); H.y = pkbf(w10, w11);
    H.z = pkbf(w20, w21); H.w = pkbf(w30, w31);
    uint4 V;
    if (hl == 0) V = H;
    else {
        V.x = pkbf(w00 - bf_lo(H.x), w01 - bf_hi(H.x));
        V.y = pkbf(w10 - bf_lo(H.y), w11 - bf_hi(H.y));
        V.z = pkbf(w20 - bf_lo(H.z), w21 - bf_hi(H.z));
        V.w = pkbf(w30 - bf_lo(H.w), w31 - bf_hi(H.w));
    }
    *(uint4*)(g_Wf + ((((size_t)((t * 4 + jt) * 4 + kt) * 2 + hl) * 32 + lane) * 4)) = V;
}

// ---------------- K1: factored layer-1 terms (4 nodes/block) ----------------
__global__ __launch_bounds__(256) void k1_precompute(
    const float* __restrict__ x,
    const float* __restrict__ e0w1, const float* __restrict__ e0b1,
    const float* __restrict__ e1w1, const float* __restrict__ e1b1)
{
    int tid  = threadIdx.x;
    int node = tid >> 6;
    int j    = tid & 63;
    int bn   = blockIdx.x * 4 + node;

    __shared__ float xs[4][DN];
    if (j < DN) xs[node][j] = x[bn * DN + j];
    __syncthreads();

    float a0 = 0.f, a1 = 0.f, c0 = e0b1[j], c1 = e1b1[j];
#pragma unroll
    for (int i = 0; i < DN; i++) {
        float xv = xs[node][i];
        a0 += xv * e0w1[i * HDIM + j];
        c0 += xv * e0w1[(DN + i) * HDIM + j];
        a1 += xv * e1w1[i * HDIM + j];
        c1 += xv * e1w1[(DN + i) * HDIM + j];
    }
    g_A0[bn * HDIM + j] = a0;
    g_C0[bn * HDIM + j] = c0;
    g_A1[bn * HDIM + j] = a1;
    g_C1[bn * HDIM + j] = c1;
}

// ---------------- K2: 3-split bf16 mma; warp = (recv, j-half, sender-half) --------
// block = (b, type, recv-pair), 256 thr = 8 warps.
// Each warp: 2 j-tiles x 4 sender-tiles -> 96 HMMA, 32 LDS.64.
// Partial messages combined across the two sender-half warps via smem.
__global__ __launch_bounds__(256, 3) void k2_mma(
    const float* __restrict__ etypes,
    const float* __restrict__ e0b2, const float* __restrict__ e1b2)
{
    __shared__ uint32_t Hw[4 * PL];          // [recv][hl] planes, bank-permuted kt tiles
    __shared__ float cbuf[2][HDIM];
    __shared__ float wts[2][NAG];
    __shared__ float b2s[HDIM];
    __shared__ float msum[2][2][HDIM];       // [sh][rl][j] partial messages

    int blk = blockIdx.x;                 // BATCH * 2 * 32
    int rp  = blk & 31;
    int t   = (blk >> 5) & 1;
    int b   = blk >> 6;
    int tid = threadIdx.x;
    int w   = tid >> 5;
    int lane = tid & 31;
    int g4  = lane >> 2, t4 = lane & 3;

    const float* At  = (t ? g_A1 : g_A0) + (long)(b * NAG) * HDIM;
    const float* Ct  = (t ? g_C1 : g_C0) + (long)(b * NAG) * HDIM;
    const float* b2t = t ? e1b2 : e0b2;

    int rl = w >> 2;          // receiver in pair: 0,1
    int jh = (w >> 1) & 1;    // j half: 0,1
    int sh = w & 1;           // sender half: 0,1
    int jt0 = jh * 2, jt1 = jh * 2 + 1;

    // small loads: C rows (2 recv), edge weights, bias
    if (tid < 128) {
        int rr = tid >> 6, k = tid & 63;
        int r  = rp * 2 + rr;
        cbuf[rr][k] = Ct[r * HDIM + k];
        int s = k;
        float wt = 0.f;
        if (s != r) {
            int e = s * 63 + r - (r > s ? 1 : 0);   // np.where(ones-eye) ordering
            wt = etypes[((long)b * NEDGE + e) * 3 + 1 + t];
        }
        wts[rr][s] = wt;
    } else if (tid < 192) {
        b2s[tid - 128] = b2t[tid - 128];
    }
    __syncthreads();

    // ---- build H fragments (hi/lo) for both receivers; A read ONCE ----
    {
        const float4* A4 = (const float4*)At;
        const float4* C4 = (const float4*)cbuf;
        float4 av[4];
#pragma unroll
        for (int it = 0; it < 4; it++) av[it] = A4[it * 256 + tid];
#pragma unroll
        for (int it = 0; it < 4; it++) {
            int idx = it * 256 + tid;          // s = idx>>4 (0..63), q = idx&15
            int s = idx >> 4, q = idx & 15;
            int kt = q >> 2;
            int lp = (q & 1) * 2;              // lane k-part
            int rr = (q >> 1) & 1;             // reg index (b0/b1)
            int st = s >> 3;
            int lb = lp + (s & 7) * 4;         // lane base
            int tbase = KTS(kt) + st * STR;    // bank-permuted tile base
            float4 a = av[it];
#pragma unroll
            for (int recv = 0; recv < 2; recv++) {
                float4 c = C4[recv * 16 + q];
                float h0 = fmaxf(a.x + c.x, 0.f), h1 = fmaxf(a.y + c.y, 0.f);
                float h2 = fmaxf(a.z + c.z, 0.f), h3 = fmaxf(a.w + c.w, 0.f);
                uint32_t P0h = pkbf(h0, h1), P1h = pkbf(h2, h3);
                uint32_t P0l = pkbf(h0 - bf_lo(P0h), h1 - bf_hi(P0h));
                uint32_t P1l = pkbf(h2 - bf_lo(P1h), h3 - bf_hi(P1h));
                int bh = (recv * 2 + 0) * PL + tbase;
                int bl = (recv * 2 + 1) * PL + tbase;
                Hw[bh + lb * 2 + rr]       = P0h;
                Hw[bh + (lb + 1) * 2 + rr] = P1h;
                Hw[bl + lb * 2 + rr]       = P0l;
                Hw[bl + (lb + 1) * 2 + rr] = P1l;
            }
        }
    }
    __syncthreads();

    // ---- MMA over this warp's sender half; 2 j-tiles per warp ----
    int pb0 = (rl * 2 + 0) * PL;              // hi plane base for this recv (rl in {0,1})
    int pb1 = (rl * 2 + 1) * PL;              // lo plane base
    int j00 = jt0 * 16 + g4, j01 = j00 + 8;
    int j10 = jt1 * 16 + g4, j11 = j10 + 8;
    float b00 = b2s[j00], b01 = b2s[j01];
    float b10 = b2s[j10], b11 = b2s[j11];
    const float* wrow = wts[rl];
    const uint4* Wf0 = (const uint4*)(g_Wf + (((size_t)(t * 4 + jt0) * 4) * 2) * 128);
    const uint4* Wf1 = (const uint4*)(g_Wf + (((size_t)(t * 4 + jt1) * 4) * 2) * 128);

    float C0[4][4], C1[4][4];
#pragma unroll
    for (int st = 0; st < 4; st++)
#pragma unroll
        for (int i = 0; i < 4; i++) { C0[st][i] = 0.f; C1[st][i] = 0.f; }

#pragma unroll
    for (int kt = 0; kt < 4; kt++) {
        uint4 wh0 = Wf0[(kt * 2 + 0) * 32 + lane];
        uint4 wl0 = Wf0[(kt * 2 + 1) * 32 + lane];
        uint4 wh1 = Wf1[(kt * 2 + 0) * 32 + lane];
        uint4 wl1 = Wf1[(kt * 2 + 1) * 32 + lane];
        int kbh = pb0 + KTS(kt) + sh * 4 * STR;
        int kbl = pb1 + KTS(kt) + sh * 4 * STR;
#pragma unroll
        for (int sp = 0; sp < 4; sp += 2) {
            uint2 h0h = *(const uint2*)(Hw + kbh + sp * STR + lane * 2);
            uint2 h1h = *(const uint2*)(Hw + kbh + (sp + 1) * STR + lane * 2);
            uint2 h0l = *(const uint2*)(Hw + kbl + sp * STR + lane * 2);
            uint2 h1l = *(const uint2*)(Hw + kbl + (sp + 1) * STR + lane * 2);
            mma_bf16(C0[sp],     wh0, h0h);
            mma_bf16(C0[sp + 1], wh0, h1h);
            mma_bf16(C1[sp],     wh1, h0h);
            mma_bf16(C1[sp + 1], wh1, h1h);
            mma_bf16(C0[sp],     wh0, h0l);
            mma_bf16(C0[sp + 1], wh0, h1l);
            mma_bf16(C1[sp],     wh1, h0l);
            mma_bf16(C1[sp + 1], wh1, h1l);
            mma_bf16(C0[sp],     wl0, h0h);
            mma_bf16(C0[sp + 1], wl0, h1h);
            mma_bf16(C1[sp],     wl1, h0h);
            mma_bf16(C1[sp + 1], wl1, h1h);
        }
    }

    // ---- fold, cross-lane reduce, stage partials ----
    float a00 = 0.f, a01 = 0.f, a10 = 0.f, a11 = 0.f;
#pragma unroll
    for (int st = 0; st < 4; st++) {
        int s0 = (sh * 4 + st) * 8 + 2 * t4;
        float2 wv = *(const float2*)(wrow + s0);
        a00 += wv.x * fmaxf(C0[st][0] + b00, 0.f)
             + wv.y * fmaxf(C0[st][1] + b00, 0.f);
        a01 += wv.x * fmaxf(C0[st][2] + b01, 0.f)
             + wv.y * fmaxf(C0[st][3] + b01, 0.f);
        a10 += wv.x * fmaxf(C1[st][0] + b10, 0.f)
             + wv.y * fmaxf(C1[st][1] + b10, 0.f);
        a11 += wv.x * fmaxf(C1[st][2] + b11, 0.f)
             + wv.y * fmaxf(C1[st][3] + b11, 0.f);
    }
    a00 += __shfl_xor_sync(0xffffffffu, a00, 1);
    a00 += __shfl_xor_sync(0xffffffffu, a00, 2);
    a01 += __shfl_xor_sync(0xffffffffu, a01, 1);
    a01 += __shfl_xor_sync(0xffffffffu, a01, 2);
    a10 += __shfl_xor_sync(0xffffffffu, a10, 1);
    a10 += __shfl_xor_sync(0xffffffffu, a10, 2);
    a11 += __shfl_xor_sync(0xffffffffu, a11, 1);
    a11 += __shfl_xor_sync(0xffffffffu, a11, 2);
    if (t4 == 0) {
        msum[sh][rl][j00] = a00;
        msum[sh][rl][j01] = a01;
        msum[sh][rl][j10] = a10;
        msum[sh][rl][j11] = a11;
    }
    __syncthreads();

    // ---- combine sender halves, write per-type message ----
    if (tid < 128) {
        int rr = tid >> 6, j = tid & 63;
        int r = rp * 2 + rr;
        g_msgT[(((long)t * BATCH + b) * NAG + r) * HDIM + j] =
            msum[0][rr][j] + msum[1][rr][j];
    }
}

// ---------------- K3: node decoder, 8 nodes/block, transposed weights --------
// w1t[j][i] stride 84 -> both dot-product operands read via LDS.128.
__global__ __launch_bounds__(512) void k3_decode(
    const float* __restrict__ x,
    const float* __restrict__ ndw1, const float* __restrict__ ndb1,
    const float* __restrict__ ndw2, const float* __restrict__ ndb2,
    float* __restrict__ out)
{
    __shared__ __align__(16) float w1t[HDIM * 84];   // transposed, padded
    __shared__ float w2s[HDIM * DOUT];
    __shared__ __align__(16) float ins[8][84];       // [x(16) | msg(64)] padded
    __shared__ float hs[8][HDIM];

    int tid  = threadIdx.x;
    int node = tid >> 6;
    int j    = tid & 63;
    int bn   = blockIdx.x * 8 + node;

    // load W1 transposed (one-time; minor STS conflicts acceptable)
#pragma unroll
    for (int it = 0; it < 10; it++) {
        int idx = it * 512 + tid;
        int i = idx >> 6, jj = idx & 63;
        w1t[jj * 84 + i] = ndw1[idx];
    }
#pragma unroll
    for (int it = 0; it < 2; it++) w2s[it * 512 + tid] = ndw2[it * 512 + tid];

    if (j < DN) ins[node][j] = x[bn * DN + j];
    ins[node][DN + j] = g_msgT[(long)bn * HDIM + j] +
                        g_msgT[(long)(BATCH * NAG + bn) * HDIM + j];
    __syncthreads();

    {
        const float4* wr = (const float4*)(w1t + j * 84);
        const float4* ir = (const float4*)(ins[node]);
        float h = ndb1[j];
#pragma unroll
        for (int i4 = 0; i4 < 20; i4++) {
            float4 wv = wr[i4];
            float4 iv = ir[i4];
            h = fmaf(iv.x, wv.x, h);
            h = fmaf(iv.y, wv.y, h);
            h = fmaf(iv.z, wv.z, h);
            h = fmaf(iv.w, wv.w, h);
        }
        hs[node][j] = fmaxf(h, 0.f);
    }
    __syncthreads();

    if (j < DOUT) {
        float o = ndb2[j];
#pragma unroll
        for (int k = 0; k < HDIM; k++) o = fmaf(hs[node][k], w2s[k * DOUT + j], o);
        out[bn * DOUT + j] = fmaxf(o, 0.f);
    }
}

extern "C" void kernel_launch(void* const* d_in, const int* in_sizes, int n_in,
                              void* d_out, int out_size)
{
    const float* node_states = (const float*)d_in[0];
    const float* edge_types  = (const float*)d_in[1];
    const float* e0_w1 = (const float*)d_in[2];
    const float* e0_b1 = (const float*)d_in[3];
    const float* e0_w2 = (const float*)d_in[4];
    const float* e0_b2 = (const float*)d_in[5];
    const float* e1_w1 = (const float*)d_in[6];
    const float* e1_b1 = (const float*)d_in[7];
    const float* e1_w2 = (const float*)d_in[8];
    const float* e1_b2 = (const float*)d_in[9];
    const float* nd_w1 = (const float*)d_in[10];
    const float* nd_b1 = (const float*)d_in[11];
    const float* nd_w2 = (const float*)d_in[12];
    const float* nd_b2 = (const float*)d_in[13];
    float* out = (float*)d_out;

    k0_wfrag<<<32, 64>>>(e0_w2, e1_w2);
    k1_precompute<<<BATCH * NAG / 4, 256>>>(node_states, e0_w1, e0_b1, e1_w1, e1_b1);
    k2_mma<<<BATCH * 2 * 32, 256>>>(edge_types, e0_b2, e1_b2);
    k3_decode<<<BATCH * NAG / 8, 512>>>(node_states, nd_w1, nd_b1, nd_w2, nd_b2, out);
}

// round 17
// speedup vs baseline: 1.4576x; 1.4576x over previous
#include <cuda_runtime.h>
#include <cstdint>

#define BATCH 128
#define NAG   64
#define NEDGE 4032
#define DN    16
#define HDIM  64
#define DOUT  16

// ---------------- scratch (no cudaMalloc) ----------------
__device__ float g_A0[BATCH * NAG * HDIM];
__device__ float g_C0[BATCH * NAG * HDIM];
__device__ float g_A1[BATCH * NAG * HDIM];
__device__ float g_C1[BATCH * NAG * HDIM];
__device__ float g_msgT[2 * BATCH * NAG * HDIM];
// W2 A-operand fp16 fragments: [t][jt(4)][kt(4)][lane(32)][4] u32 (f16x2)
__device__ uint32_t g_Wf[2 * 4 * 4 * 32 * 4];

// ---------------- helpers ----------------
// pack two floats -> f16x2, low half = first (lower-k) element
__device__ __forceinline__ uint32_t pkhf(float lok, float hik) {
    uint32_t d;
    asm("cvt.rn.f16x2.f32 %0, %1, %2;" : "=r"(d) : "f"(hik), "f"(lok));
    return d;
}

__device__ __forceinline__ void mma_f16(float c[4], uint4 a, uint2 b) {
    asm volatile(
        "mma.sync.aligned.m16n8k16.row.col.f32.f16.f16.f32 "
        "{%0,%1,%2,%3}, {%4,%5,%6,%7}, {%8,%9}, {%0,%1,%2,%3};"
        : "+f"(c[0]), "+f"(c[1]), "+f"(c[2]), "+f"(c[3])
        : "r"(a.x), "r"(a.y), "r"(a.z), "r"(a.w), "r"(b.x), "r"(b.y));
}

// Hw layout (R14-proven conflict-free): per-recv plane stride PL; kt tiles at
// KTS(kt) = kt*576 + {0,2,16,18} bank perm; st rows stride 68.
#define STR  68
#define KTS(kt) ((kt) * 576 + (((kt) & 1) * 2) + (((kt) >> 1) * 16))
#define PL   2304

// ---------------- K0: W2 -> fp16 A-operand fragments ----------------
__global__ __launch_bounds__(32) void k0_wfrag(
    const float* __restrict__ e0w2, const float* __restrict__ e1w2)
{
    int blk = blockIdx.x;              // 0..31 : t*16 + jt*4 + kt
    int t  = blk >> 4;
    int jt = (blk >> 2) & 3;
    int kt = blk & 3;
    int lane = threadIdx.x;
    int g4 = lane >> 2, t4 = lane & 3;

    const float* w2t = t ? e1w2 : e0w2;
    int K0 = kt * 16 + 2 * t4;
    int J  = jt * 16 + g4;

    uint4 V;
    V.x = pkhf(w2t[K0 * HDIM + J],           w2t[(K0 + 1) * HDIM + J]);
    V.y = pkhf(w2t[K0 * HDIM + J + 8],       w2t[(K0 + 1) * HDIM + J + 8]);
    V.z = pkhf(w2t[(K0 + 8) * HDIM + J],     w2t[(K0 + 9) * HDIM + J]);
    V.w = pkhf(w2t[(K0 + 8) * HDIM + J + 8], w2t[(K0 + 9) * HDIM + J + 8]);
    *(uint4*)(g_Wf + (((size_t)((t * 4 + jt) * 4 + kt) * 32 + lane) * 4)) = V;
}

// ---------------- K1: factored layer-1 terms (4 nodes/block) ----------------
__global__ __launch_bounds__(256) void k1_precompute(
    const float* __restrict__ x,
    const float* __restrict__ e0w1, const float* __restrict__ e0b1,
    const float* __restrict__ e1w1, const float* __restrict__ e1b1)
{
    int tid  = threadIdx.x;
    int node = tid >> 6;
    int j    = tid & 63;
    int bn   = blockIdx.x * 4 + node;

    __shared__ float xs[4][DN];
    if (j < DN) xs[node][j] = x[bn * DN + j];
    __syncthreads();

    float a0 = 0.f, a1 = 0.f, c0 = e0b1[j], c1 = e1b1[j];
#pragma unroll
    for (int i = 0; i < DN; i++) {
        float xv = xs[node][i];
        a0 += xv * e0w1[i * HDIM + j];
        c0 += xv * e0w1[(DN + i) * HDIM + j];
        a1 += xv * e1w1[i * HDIM + j];
        c1 += xv * e1w1[(DN + i) * HDIM + j];
    }
    g_A0[bn * HDIM + j] = a0;
    g_C0[bn * HDIM + j] = c0;
    g_A1[bn * HDIM + j] = a1;
    g_C1[bn * HDIM + j] = c1;
}

// ---------------- K2: single-product fp16 mma; warp = (recv, j-half, sender-half) --
// block = (b, type, recv-pair), 256 thr = 8 warps.
// Each warp: 2 j-tiles x 4 sender-tiles x 4 kt -> 32 HMMA, 16 LDS.64.
__global__ __launch_bounds__(256, 3) void k2_mma(
    const float* __restrict__ etypes,
    const float* __restrict__ e0b2, const float* __restrict__ e1b2)
{
    __shared__ uint32_t Hw[2 * PL];          // one plane per receiver (fp16, no splits)
    __shared__ float cbuf[2][HDIM];
    __shared__ float wts[2][NAG];
    __shared__ float b2s[HDIM];
    __shared__ float msum[2][2][HDIM];       // [sh][rl][j] partial messages

    int blk = blockIdx.x;                 // BATCH * 2 * 32
    int rp  = blk & 31;
    int t   = (blk >> 5) & 1;
    int b   = blk >> 6;
    int tid = threadIdx.x;
    int w   = tid >> 5;
    int lane = tid & 31;
    int g4  = lane >> 2, t4 = lane & 3;

    const float* At  = (t ? g_A1 : g_A0) + (long)(b * NAG) * HDIM;
    const float* Ct  = (t ? g_C1 : g_C0) + (long)(b * NAG) * HDIM;
    const float* b2t = t ? e1b2 : e0b2;

    int rl = w >> 2;          // receiver in pair: 0,1
    int jh = (w >> 1) & 1;    // j half: 0,1
    int sh = w & 1;           // sender half: 0,1
    int jt0 = jh * 2, jt1 = jh * 2 + 1;

    // small loads: C rows (2 recv), edge weights, bias
    if (tid < 128) {
        int rr = tid >> 6, k = tid & 63;
        int r  = rp * 2 + rr;
        cbuf[rr][k] = Ct[r * HDIM + k];
        int s = k;
        float wt = 0.f;
        if (s != r) {
            int e = s * 63 + r - (r > s ? 1 : 0);   // np.where(ones-eye) ordering
            wt = etypes[((long)b * NEDGE + e) * 3 + 1 + t];
        }
        wts[rr][s] = wt;
    } else if (tid < 192) {
        b2s[tid - 128] = b2t[tid - 128];
    }
    __syncthreads();

    // ---- build fp16 H fragments for both receivers; A read ONCE ----
    {
        const float4* A4 = (const float4*)At;
        const float4* C4 = (const float4*)cbuf;
        float4 av[4];
#pragma unroll
        for (int it = 0; it < 4; it++) av[it] = A4[it * 256 + tid];
#pragma unroll
        for (int it = 0; it < 4; it++) {
            int idx = it * 256 + tid;          // s = idx>>4 (0..63), q = idx&15
            int s = idx >> 4, q = idx & 15;
            int kt = q >> 2;
            int lp = (q & 1) * 2;              // lane k-part
            int rr = (q >> 1) & 1;             // reg index (b0/b1)
            int st = s >> 3;
            int lb = lp + (s & 7) * 4;         // lane base
            int tbase = KTS(kt) + st * STR;    // bank-permuted tile base
            float4 a = av[it];
#pragma unroll
            for (int recv = 0; recv < 2; recv++) {
                float4 c = C4[recv * 16 + q];
                float h0 = fmaxf(a.x + c.x, 0.f), h1 = fmaxf(a.y + c.y, 0.f);
                float h2 = fmaxf(a.z + c.z, 0.f), h3 = fmaxf(a.w + c.w, 0.f);
                int bh = recv * PL + tbase;
                Hw[bh + lb * 2 + rr]       = pkhf(h0, h1);
                Hw[bh + (lb + 1) * 2 + rr] = pkhf(h2, h3);
            }
        }
    }
    __syncthreads();

    // ---- MMA over this warp's sender half; 2 j-tiles per warp ----
    int pb = rl * PL;
    int j00 = jt0 * 16 + g4, j01 = j00 + 8;
    int j10 = jt1 * 16 + g4, j11 = j10 + 8;
    float b00 = b2s[j00], b01 = b2s[j01];
    float b10 = b2s[j10], b11 = b2s[j11];
    const float* wrow = wts[rl];
    const uint4* Wf0 = (const uint4*)(g_Wf + ((size_t)(t * 4 + jt0) * 4) * 128);
    const uint4* Wf1 = (const uint4*)(g_Wf + ((size_t)(t * 4 + jt1) * 4) * 128);

    float C0[4][4], C1[4][4];
#pragma unroll
    for (int st = 0; st < 4; st++)
#pragma unroll
        for (int i = 0; i < 4; i++) { C0[st][i] = 0.f; C1[st][i] = 0.f; }

#pragma unroll
    for (int kt = 0; kt < 4; kt++) {
        uint4 wh0 = Wf0[kt * 32 + lane];
        uint4 wh1 = Wf1[kt * 32 + lane];
        int kb = pb + KTS(kt) + sh * 4 * STR;
#pragma unroll
        for (int sp = 0; sp < 4; sp += 2) {
            uint2 h0 = *(const uint2*)(Hw + kb + sp * STR + lane * 2);
            uint2 h1 = *(const uint2*)(Hw + kb + (sp + 1) * STR + lane * 2);
            mma_f16(C0[sp],     wh0, h0);
            mma_f16(C0[sp + 1], wh0, h1);
            mma_f16(C1[sp],     wh1, h0);
            mma_f16(C1[sp + 1], wh1, h1);
        }
    }

    // ---- fold, cross-lane reduce, stage partials ----
    float a00 = 0.f, a01 = 0.f, a10 = 0.f, a11 = 0.f;
#pragma unroll
    for (int st = 0; st < 4; st++) {
        int s0 = (sh * 4 + st) * 8 + 2 * t4;
        float2 wv = *(const float2*)(wrow + s0);
        a00 += wv.x * fmaxf(C0[st][0] + b00, 0.f)
             + wv.y * fmaxf(C0[st][1] + b00, 0.f);
        a01 += wv.x * fmaxf(C0[st][2] + b01, 0.f)
             + wv.y * fmaxf(C0[st][3] + b01, 0.f);
        a10 += wv.x * fmaxf(C1[st][0] + b10, 0.f)
             + wv.y * fmaxf(C1[st][1] + b10, 0.f);
        a11 += wv.x * fmaxf(C1[st][2] + b11, 0.f)
             + wv.y * fmaxf(C1[st][3] + b11, 0.f);
    }
    a00 += __shfl_xor_sync(0xffffffffu, a00, 1);
    a00 += __shfl_xor_sync(0xffffffffu, a00, 2);
    a01 += __shfl_xor_sync(0xffffffffu, a01, 1);
    a01 += __shfl_xor_sync(0xffffffffu, a01, 2);
    a10 += __shfl_xor_sync(0xffffffffu, a10, 1);
    a10 += __shfl_xor_sync(0xffffffffu, a10, 2);
    a11 += __shfl_xor_sync(0xffffffffu, a11, 1);
    a11 += __shfl_xor_sync(0xffffffffu, a11, 2);
    if (t4 == 0) {
        msum[sh][rl][j00] = a00;
        msum[sh][rl][j01] = a01;
        msum[sh][rl][j10] = a10;
        msum[sh][rl][j11] = a11;
    }
    __syncthreads();

    // ---- combine sender halves, write per-type message ----
    if (tid < 128) {
        int rr = tid >> 6, j = tid & 63;
        int r = rp * 2 + rr;
        g_msgT[(((long)t * BATCH + b) * NAG + r) * HDIM + j] =
            msum[0][rr][j] + msum[1][rr][j];
    }
}

// ---------------- K3: node decoder, 8 nodes/block, smem-cached weights --------
// (reverted to the R13 version — the transposed variant regressed)
__global__ __launch_bounds__(512) void k3_decode(
    const float* __restrict__ x,
    const float* __restrict__ ndw1, const float* __restrict__ ndb1,
    const float* __restrict__ ndw2, const float* __restrict__ ndb2,
    float* __restrict__ out)
{
    __shared__ float w1s[(DN + HDIM) * HDIM];   // 5120 f = 20 KB
    __shared__ float w2s[HDIM * DOUT];          // 1024 f = 4 KB
    __shared__ float xs[8][DN];
    __shared__ float ms[8][HDIM];
    __shared__ float hs[8][HDIM];

    int tid  = threadIdx.x;
    int node = tid >> 6;
    int j    = tid & 63;
    int bn   = blockIdx.x * 8 + node;

#pragma unroll
    for (int i = 0; i < 10; i++) w1s[i * 512 + tid] = ndw1[i * 512 + tid];
#pragma unroll
    for (int i = 0; i < 2; i++)  w2s[i * 512 + tid] = ndw2[i * 512 + tid];

    if (j < DN) xs[node][j] = x[bn * DN + j];
    ms[node][j] = g_msgT[(long)bn * HDIM + j] +
                  g_msgT[(long)(BATCH * NAG + bn) * HDIM + j];
    __syncthreads();

    float h = ndb1[j];
#pragma unroll
    for (int i = 0; i < DN; i++)   h = fmaf(xs[node][i], w1s[i * HDIM + j], h);
#pragma unroll
    for (int k = 0; k < HDIM; k++) h = fmaf(ms[node][k], w1s[(DN + k) * HDIM + j], h);
    hs[node][j] = fmaxf(h, 0.f);
    __syncthreads();

    if (j < DOUT) {
        float o = ndb2[j];
#pragma unroll
        for (int k = 0; k < HDIM; k++) o = fmaf(hs[node][k], w2s[k * DOUT + j], o);
        out[bn * DOUT + j] = fmaxf(o, 0.f);
    }
}

extern "C" void kernel_launch(void* const* d_in, const int* in_sizes, int n_in,
                              void* d_out, int out_size)
{
    const float* node_states = (const float*)d_in[0];
    const float* edge_types  = (const float*)d_in[1];
    const float* e0_w1 = (const float*)d_in[2];
    const float* e0_b1 = (const float*)d_in[3];
    const float* e0_w2 = (const float*)d_in[4];
    const float* e0_b2 = (const float*)d_in[5];
    const float* e1_w1 = (const float*)d_in[6];
    const float* e1_b1 = (const float*)d_in[7];
    const float* e1_w2 = (const float*)d_in[8];
    const float* e1_b2 = (const float*)d_in[9];
    const float* nd_w1 = (const float*)d_in[10];
    const float* nd_b1 = (const float*)d_in[11];
    const float* nd_w2 = (const float*)d_in[12];
    const float* nd_b2 = (const float*)d_in[13];
    float* out = (float*)d_out;

    k0_wfrag<<<32, 32>>>(e0_w2, e1_w2);
    k1_precompute<<<BATCH * NAG / 4, 256>>>(node_states, e0_w1, e0_b1, e1_w1, e1_b1);
    k2_mma<<<BATCH * 2 * 32, 256>>>(edge_types, e0_b2, e1_b2);
    k3_decode<<<BATCH * NAG / 8, 512>>>(node_states, nd_w1, nd_b1, nd_w2, nd_b2, out);
}